// round 16
// baseline (speedup 1.0000x reference)
#include <cuda_runtime.h>
#include <cuda_fp16.h>
#include <cstddef>
#include <cstdint>

#define BB 256      // batch
#define TT 2048     // time steps
#define HH 64       // hidden
#define GG 256      // 4*H gates

typedef unsigned long long u64;

// ---------------- packed f32x2 helpers (sm_100+) ----------------
__device__ __forceinline__ u64 fma2(u64 a, u64 b, u64 c) {
    u64 d;
    asm("fma.rn.f32x2 %0, %1, %2, %3;" : "=l"(d) : "l"(a), "l"(b), "l"(c));
    return d;
}
__device__ __forceinline__ u64 add2(u64 a, u64 b) {
    u64 d;
    asm("add.rn.f32x2 %0, %1, %2;" : "=l"(d) : "l"(a), "l"(b));
    return d;
}
__device__ __forceinline__ float hsum2(u64 a) {
    float lo = __uint_as_float((unsigned)(a & 0xffffffffull));
    float hi = __uint_as_float((unsigned)(a >> 32));
    return lo + hi;
}

// MUFU-based fast activations
__device__ __forceinline__ float tanh_ap(float x) {
    float y;
    asm("tanh.approx.f32 %0, %1;" : "=f"(y) : "f"(x));
    return y;
}
__device__ __forceinline__ float sig_ap(float x) {
    return fmaf(0.5f, tanh_ap(0.5f * x), 0.5f);
}

// cp.async helpers (sm_80+; LDGSTS on sm_103a)
__device__ __forceinline__ void cp_async16(uint32_t smem_addr, const void* gptr) {
    asm volatile("cp.async.cg.shared.global [%0], [%1], 16;"
                 :: "r"(smem_addr), "l"(gptr) : "memory");
}
__device__ __forceinline__ void cp_commit() {
    asm volatile("cp.async.commit_group;" ::: "memory");
}
template <int N>
__device__ __forceinline__ void cp_wait() {
    asm volatile("cp.async.wait_group %0;" :: "n"(N) : "memory");
}
__device__ __forceinline__ uint32_t smem_u32(const void* p) {
    uint32_t a;
    asm("{ .reg .u64 t; cvta.to.shared.u64 t, %1; cvt.u32.u64 %0, t; }"
        : "=r"(a) : "l"(p));
    return a;
}

// ---------------- device scratch (no cudaMalloc allowed) ----------------
__device__ __half g_y0h[(size_t)BB * TT * HH];    // 64 MB, layer0 outputs (fp16)
__device__ __half g_xp1[(size_t)BB * TT * GG];    // 256 MB, xp natural layout (fp16)
__device__ float  g_y1[(size_t)BB * TT * HH];     // 128 MB, layer1 outputs

// ---------------- Layer 0 recurrence (PROVEN, unchanged) ----------------
__global__ __launch_bounds__(128, 2) void lstm_l0_kernel(
    const float* __restrict__ x,     // [B,T]
    const float* __restrict__ Wih,   // [256,1]
    const float* __restrict__ Whh,   // [256,64]
    const float* __restrict__ bih,
    const float* __restrict__ bhh,
    const float* __restrict__ h0,    // [B,64] layer0 slice
    const float* __restrict__ c0)    // [B,64]
{
    __shared__ __align__(16) float  h_sh[HH];
    __shared__ __align__(8)  float2 act_sh[HH];   // (f,o) per unit

    const int tid  = threadIdx.x;
    const int b    = blockIdx.x;
    const int g0   = tid;
    const int g1   = tid + 128;
    const int unit = tid & 63;
    const bool low = (tid < 64);

    u64 w0[32], w1[32];
    {
        const ulonglong2* r0 = (const ulonglong2*)(Whh + (size_t)g0 * HH);
        const ulonglong2* r1 = (const ulonglong2*)(Whh + (size_t)g1 * HH);
#pragma unroll
        for (int i = 0; i < 16; i++) {
            ulonglong2 v0 = r0[i];
            ulonglong2 v1 = r1[i];
            w0[2 * i] = v0.x; w0[2 * i + 1] = v0.y;
            w1[2 * i] = v1.x; w1[2 * i + 1] = v1.y;
        }
    }
    const float bias0 = bih[g0] + bhh[g0];
    const float bias1 = bih[g1] + bhh[g1];
    const float wx0 = Wih[g0];
    const float wx1 = Wih[g1];

    float c = 0.0f;
    if (low) {
        h_sh[unit] = h0[(size_t)b * HH + unit];
        c          = c0[(size_t)b * HH + unit];
    }
    __syncthreads();

    const size_t xb = (size_t)b * TT;
    const size_t yb = (size_t)b * TT * HH;

    float v[4];
#pragma unroll
    for (int k = 0; k < 4; k++) v[k] = __ldg(x + xb + k);

#pragma unroll 4
    for (int t = 0; t < TT; t++) {
        u64 a0 = 0ull, a1 = 0ull, d0 = 0ull, d1 = 0ull;
        const ulonglong2* hs = (const ulonglong2*)h_sh;
#pragma unroll
        for (int i = 0; i < 8; i++) {
            ulonglong2 h1 = hs[2 * i];
            ulonglong2 h2 = hs[2 * i + 1];
            a0 = fma2(w0[4 * i + 0], h1.x, a0);
            d0 = fma2(w1[4 * i + 0], h1.x, d0);
            a1 = fma2(w0[4 * i + 1], h1.y, a1);
            d1 = fma2(w1[4 * i + 1], h1.y, d1);
            a0 = fma2(w0[4 * i + 2], h2.x, a0);
            d0 = fma2(w1[4 * i + 2], h2.x, d0);
            a1 = fma2(w0[4 * i + 3], h2.y, a1);
            d1 = fma2(w1[4 * i + 3], h2.y, d1);
        }
        float pre0 = fmaf(v[0], wx0, bias0) + hsum2(add2(a0, a1));
        float pre1 = fmaf(v[0], wx1, bias1) + hsum2(add2(d0, d1));

        float act0 = sig_ap(pre0);                              // i or f
        float act1 = low ? tanh_ap(pre1) : sig_ap(pre1);        // g or o
        if (!low) act_sh[unit] = make_float2(act0, act1);       // (f,o)

        v[0] = v[1]; v[1] = v[2]; v[2] = v[3];
        {
            int tn = (t + 4 < TT) ? (t + 4) : (TT - 1);
            v[3] = __ldg(x + xb + tn);
        }
        __syncthreads();   // gates staged; h reads done

        if (low) {
            float2 fo = act_sh[unit];
            c = fmaf(fo.x, c, act0 * act1);
            float hv = fo.y * tanh_ap(c);
            h_sh[unit] = hv;
            g_y0h[yb + (size_t)t * HH + unit] = __float2half_rn(hv);
        }
        __syncthreads();   // h ready
    }
}

// ---------------- K2: xp = y0 @ Wih1^T, coalesced fp16 output --------------
#define K2_ROWS 64
__global__ __launch_bounds__(256, 2) void xp_gemm_kernel(const float* __restrict__ Wih1)
{
    __shared__ __align__(16) float ys[K2_ROWS * HH];
    const int g = threadIdx.x;

    u64 w[32];
    {
        const ulonglong2* wr = (const ulonglong2*)(Wih1 + (size_t)g * HH);
#pragma unroll
        for (int i = 0; i < 16; i++) {
            ulonglong2 v = wr[i];
            w[2 * i]     = v.x;
            w[2 * i + 1] = v.y;
        }
    }

    const size_t r0 = (size_t)blockIdx.x * K2_ROWS;
    {
        const __half2* src = (const __half2*)(g_y0h + r0 * HH);
        float2* dst = (float2*)ys;
#pragma unroll
        for (int i = 0; i < 8; i++) {
            __half2 v = src[g + i * 256];
            dst[g + i * 256] = __half22float2(v);
        }
    }
    __syncthreads();

#pragma unroll 1
    for (int r = 0; r < K2_ROWS; r++) {
        const ulonglong2* hs = (const ulonglong2*)(ys + r * HH);
        u64 a0 = 0ull, a1 = 0ull, a2 = 0ull, a3 = 0ull;
#pragma unroll
        for (int i = 0; i < 8; i++) {
            ulonglong2 h1 = hs[2 * i];
            ulonglong2 h2 = hs[2 * i + 1];
            a0 = fma2(w[4 * i + 0], h1.x, a0);
            a1 = fma2(w[4 * i + 1], h1.y, a1);
            a2 = fma2(w[4 * i + 2], h2.x, a2);
            a3 = fma2(w[4 * i + 3], h2.y, a3);
        }
        a0 = add2(a0, a1);
        a2 = add2(a2, a3);
        a0 = add2(a0, a2);
        g_xp1[(r0 + r) * GG + g] = __float2half_rn(hsum2(a0));   // coalesced
    }
}

// ---------------- Layer 1: xp via 8-step-block cp.async ring ----------------
// The per-SM L1tex queue is shared by LDS and global wavefronts; injecting
// DRAM traffic every step makes the critical-path LDS queue behind it. Fix:
// fetch xp in 4KB blocks (8 steps x 512B) once every 8 steps -> 7 of 8 steps
// have an L0-clean LSU pipe. Ring of 4 blocks (16KB smem), issued 3 blocks
// ahead; cp.async is NOT drained by bar.sync (PTX), waits via wait_group 3.
#define BLK 8
#define NBLK (TT / BLK)   // 256
__global__ __launch_bounds__(128, 2) void lstm_l1_kernel(
    const float* __restrict__ Whh,   // Whh1 [256,64]
    const float* __restrict__ bih,
    const float* __restrict__ bhh,
    const float* __restrict__ h0,    // [B,64] layer1 slice
    const float* __restrict__ c0)    // [B,64]
{
    __shared__ __align__(16) float  h_sh[HH];
    __shared__ __align__(8)  float2 act_sh[HH];        // (f,o) per unit
    __shared__ __align__(16) __half xbuf[4][BLK][GG];  // 16KB xp ring

    const int tid  = threadIdx.x;
    const int b    = blockIdx.x;
    const int g0   = tid;
    const int g1   = tid + 128;
    const int unit = tid & 63;
    const bool low = (tid < 64);

    u64 w0[32], w1[32];
    {
        const ulonglong2* r0 = (const ulonglong2*)(Whh + (size_t)g0 * HH);
        const ulonglong2* r1 = (const ulonglong2*)(Whh + (size_t)g1 * HH);
#pragma unroll
        for (int i = 0; i < 16; i++) {
            ulonglong2 v0 = r0[i];
            ulonglong2 v1 = r1[i];
            w0[2 * i] = v0.x; w0[2 * i + 1] = v0.y;
            w1[2 * i] = v1.x; w1[2 * i + 1] = v1.y;
        }
    }
    const float bias0 = bih[g0] + bhh[g0];
    const float bias1 = bih[g1] + bhh[g1];

    float c = 0.0f;
    if (low) {
        h_sh[unit] = h0[(size_t)b * HH + unit];
        c          = c0[(size_t)b * HH + unit];
    }

    const size_t yb = (size_t)b * TT * HH;
    const __half* xsrc = g_xp1 + (size_t)b * TT * GG;   // 256 halves per step

    // prologue: blocks 0..2 (each 4KB = 128 threads x 2 x 16B, one commit)
#pragma unroll
    for (int kb = 0; kb < 3; kb++) {
        uint32_t base = smem_u32(&xbuf[kb][0][0]);
        const __half* src = xsrc + (size_t)kb * BLK * GG;
        cp_async16(base + tid * 16,        src + tid * 8);
        cp_async16(base + 2048 + tid * 16, src + 1024 + tid * 8);
        cp_commit();
    }
    cp_wait<2>();   // block 0 resident
    __syncthreads();

#pragma unroll 8
    for (int t = 0; t < TT; t++) {
        // ---- block boundary: issue block (t/8)+3, pin block t/8 ----
        if ((t & (BLK - 1)) == 0) {
            const int nb = (t >> 3) + 3;
            if (nb < NBLK) {
                uint32_t base = smem_u32(&xbuf[nb & 3][0][0]);
                const __half* src = xsrc + (size_t)nb * BLK * GG;
                cp_async16(base + tid * 16,        src + tid * 8);
                cp_async16(base + 2048 + tid * 16, src + 1024 + tid * 8);
                cp_commit();
            }
            cp_wait<3>();   // current block (t/8) resident
            __syncthreads();
        }

        // ---- recurrent dots (critical path) ----
        u64 a0 = 0ull, a1 = 0ull, d0 = 0ull, d1 = 0ull;
        const ulonglong2* hs = (const ulonglong2*)h_sh;
#pragma unroll
        for (int i = 0; i < 8; i++) {
            ulonglong2 h1 = hs[2 * i];
            ulonglong2 h2 = hs[2 * i + 1];
            a0 = fma2(w0[4 * i + 0], h1.x, a0);
            d0 = fma2(w1[4 * i + 0], h1.x, d0);
            a1 = fma2(w0[4 * i + 1], h1.y, a1);
            d1 = fma2(w1[4 * i + 1], h1.y, d1);
            a0 = fma2(w0[4 * i + 2], h2.x, a0);
            d0 = fma2(w1[4 * i + 2], h2.x, d0);
            a1 = fma2(w0[4 * i + 3], h2.y, a1);
            d1 = fma2(w1[4 * i + 3], h2.y, d1);
        }
        const __half* xrow = &xbuf[(t >> 3) & 3][t & (BLK - 1)][0];
        float xp0 = __half2float(xrow[g0]);
        float xp1 = __half2float(xrow[g1]);
        float pre0 = (bias0 + xp0) + hsum2(add2(a0, a1));
        float pre1 = (bias1 + xp1) + hsum2(add2(d0, d1));

        float act0 = sig_ap(pre0);                              // i or f
        float act1 = low ? tanh_ap(pre1) : sig_ap(pre1);        // g or o
        if (!low) act_sh[unit] = make_float2(act0, act1);       // (f,o)

        __syncthreads();   // bar1: gates staged; h reads done

        if (low) {
            float2 fo = act_sh[unit];
            c = fmaf(fo.x, c, act0 * act1);
            float hv = fo.y * tanh_ap(c);
            h_sh[unit] = hv;
            g_y1[yb + (size_t)t * HH + unit] = hv;
        }
        __syncthreads();   // bar2: h ready
    }
}

// ---------------- out: pred = y1 @ Wlin^T + blin ----------------
__global__ __launch_bounds__(256) void out_kernel(
    const float* __restrict__ Wlin,
    const float* __restrict__ blin,
    float* __restrict__ out)
{
    __shared__ __align__(16) float wl[HH];
    const int tid = threadIdx.x;
    if (tid < HH) wl[tid] = Wlin[tid];
    __syncthreads();

    const size_t idx = (size_t)blockIdx.x * 256 + tid;
    const ulonglong2* row = (const ulonglong2*)(g_y1 + idx * HH);
    const ulonglong2* wv  = (const ulonglong2*)wl;
    u64 a0 = 0ull, a1 = 0ull, a2 = 0ull, a3 = 0ull;
#pragma unroll
    for (int i = 0; i < 8; i++) {
        ulonglong2 h1 = row[2 * i];
        ulonglong2 w1 = wv[2 * i];
        ulonglong2 h2 = row[2 * i + 1];
        ulonglong2 w2 = wv[2 * i + 1];
        a0 = fma2(w1.x, h1.x, a0);
        a1 = fma2(w1.y, h1.y, a1);
        a2 = fma2(w2.x, h2.x, a2);
        a3 = fma2(w2.y, h2.y, a3);
    }
    a0 = add2(a0, a1);
    a2 = add2(a2, a3);
    a0 = add2(a0, a2);
    out[idx] = hsum2(a0) + __ldg(blin);
}

// ---------------- launch ----------------
extern "C" void kernel_launch(void* const* d_in, const int* in_sizes, int n_in,
                              void* d_out, int out_size)
{
    const float* input = (const float*)d_in[0];   // [B,T]
    const float* h0    = (const float*)d_in[1];   // [2,B,H]
    const float* c0    = (const float*)d_in[2];   // [2,B,H]
    const float* Wih0  = (const float*)d_in[3];   // [256,1]
    const float* Whh0  = (const float*)d_in[4];   // [256,64]
    const float* bih0  = (const float*)d_in[5];
    const float* bhh0  = (const float*)d_in[6];
    const float* Wih1  = (const float*)d_in[7];   // [256,64]
    const float* Whh1  = (const float*)d_in[8];   // [256,64]
    const float* bih1  = (const float*)d_in[9];
    const float* bhh1  = (const float*)d_in[10];
    const float* Wlin  = (const float*)d_in[11];  // [1,64]
    const float* blin  = (const float*)d_in[12];  // [1]
    float* out = (float*)d_out;                   // [B,T]

    (void)in_sizes; (void)n_in; (void)out_size;

    // Layer 0 -> g_y0h (fp16)
    lstm_l0_kernel<<<BB, 128>>>(input, Wih0, Whh0, bih0, bhh0, h0, c0);
    // xp = y0 @ Wih1^T -> g_xp1 (fp16, coalesced)
    xp_gemm_kernel<<<(BB * TT) / K2_ROWS, 256>>>(Wih1);
    // Layer 1 (8-step-block cp.async xp ring) -> g_y1
    lstm_l1_kernel<<<BB, 128>>>(Whh1, bih1, bhh1,
                                h0 + (size_t)BB * HH, c0 + (size_t)BB * HH);
    // pred = y1 @ Wlin^T + blin
    out_kernel<<<(BB * TT) / 256, 256>>>(Wlin, blin, out);
}

// round 17
// speedup vs baseline: 1.0003x; 1.0003x over previous
#include <cuda_runtime.h>
#include <cuda_fp16.h>
#include <cstddef>
#include <cstdint>

#define BB 256      // batch
#define TT 2048     // time steps
#define HH 64       // hidden
#define GG 256      // 4*H gates

typedef unsigned long long u64;

// ---------------- packed f32x2 helpers (sm_100+) ----------------
__device__ __forceinline__ u64 fma2(u64 a, u64 b, u64 c) {
    u64 d;
    asm("fma.rn.f32x2 %0, %1, %2, %3;" : "=l"(d) : "l"(a), "l"(b), "l"(c));
    return d;
}
__device__ __forceinline__ u64 add2(u64 a, u64 b) {
    u64 d;
    asm("add.rn.f32x2 %0, %1, %2;" : "=l"(d) : "l"(a), "l"(b));
    return d;
}
__device__ __forceinline__ float hsum2(u64 a) {
    float lo = __uint_as_float((unsigned)(a & 0xffffffffull));
    float hi = __uint_as_float((unsigned)(a >> 32));
    return lo + hi;
}

// MUFU-based fast activations
__device__ __forceinline__ float tanh_ap(float x) {
    float y;
    asm("tanh.approx.f32 %0, %1;" : "=f"(y) : "f"(x));
    return y;
}
__device__ __forceinline__ float sig_ap(float x) {
    return fmaf(0.5f, tanh_ap(0.5f * x), 0.5f);
}

// cp.async helpers (sm_80+; LDGSTS on sm_103a)
__device__ __forceinline__ void cp_async16(uint32_t smem_addr, const void* gptr) {
    asm volatile("cp.async.cg.shared.global [%0], [%1], 16;"
                 :: "r"(smem_addr), "l"(gptr) : "memory");
}
__device__ __forceinline__ void cp_commit() {
    asm volatile("cp.async.commit_group;" ::: "memory");
}
template <int N>
__device__ __forceinline__ void cp_wait() {
    asm volatile("cp.async.wait_group %0;" :: "n"(N) : "memory");
}
__device__ __forceinline__ uint32_t smem_u32(const void* p) {
    uint32_t a;
    asm("{ .reg .u64 t; cvta.to.shared.u64 t, %1; cvt.u32.u64 %0, t; }"
        : "=r"(a) : "l"(p));
    return a;
}

// ---------------- device scratch (no cudaMalloc allowed) ----------------
__device__ __half g_y0h[(size_t)BB * TT * HH];    // 64 MB, layer0 outputs (fp16)
__device__ __half g_xp1[(size_t)BB * TT * GG];    // 256 MB, xp natural layout (fp16)
__device__ float  g_y1[(size_t)BB * TT * HH];     // 128 MB, layer1 outputs

// ---------------- Layer 0 recurrence (PROVEN, unchanged) ----------------
__global__ __launch_bounds__(128, 2) void lstm_l0_kernel(
    const float* __restrict__ x,     // [B,T]
    const float* __restrict__ Wih,   // [256,1]
    const float* __restrict__ Whh,   // [256,64]
    const float* __restrict__ bih,
    const float* __restrict__ bhh,
    const float* __restrict__ h0,    // [B,64] layer0 slice
    const float* __restrict__ c0)    // [B,64]
{
    __shared__ __align__(16) float  h_sh[HH];
    __shared__ __align__(8)  float2 act_sh[HH];   // (f,o) per unit

    const int tid  = threadIdx.x;
    const int b    = blockIdx.x;
    const int g0   = tid;
    const int g1   = tid + 128;
    const int unit = tid & 63;
    const bool low = (tid < 64);

    u64 w0[32], w1[32];
    {
        const ulonglong2* r0 = (const ulonglong2*)(Whh + (size_t)g0 * HH);
        const ulonglong2* r1 = (const ulonglong2*)(Whh + (size_t)g1 * HH);
#pragma unroll
        for (int i = 0; i < 16; i++) {
            ulonglong2 v0 = r0[i];
            ulonglong2 v1 = r1[i];
            w0[2 * i] = v0.x; w0[2 * i + 1] = v0.y;
            w1[2 * i] = v1.x; w1[2 * i + 1] = v1.y;
        }
    }
    const float bias0 = bih[g0] + bhh[g0];
    const float bias1 = bih[g1] + bhh[g1];
    const float wx0 = Wih[g0];
    const float wx1 = Wih[g1];

    float c = 0.0f;
    if (low) {
        h_sh[unit] = h0[(size_t)b * HH + unit];
        c          = c0[(size_t)b * HH + unit];
    }
    __syncthreads();

    const size_t xb = (size_t)b * TT;
    const size_t yb = (size_t)b * TT * HH;

    float v[4];
#pragma unroll
    for (int k = 0; k < 4; k++) v[k] = __ldg(x + xb + k);

#pragma unroll 4
    for (int t = 0; t < TT; t++) {
        u64 a0 = 0ull, a1 = 0ull, d0 = 0ull, d1 = 0ull;
        const ulonglong2* hs = (const ulonglong2*)h_sh;
#pragma unroll
        for (int i = 0; i < 8; i++) {
            ulonglong2 h1 = hs[2 * i];
            ulonglong2 h2 = hs[2 * i + 1];
            a0 = fma2(w0[4 * i + 0], h1.x, a0);
            d0 = fma2(w1[4 * i + 0], h1.x, d0);
            a1 = fma2(w0[4 * i + 1], h1.y, a1);
            d1 = fma2(w1[4 * i + 1], h1.y, d1);
            a0 = fma2(w0[4 * i + 2], h2.x, a0);
            d0 = fma2(w1[4 * i + 2], h2.x, d0);
            a1 = fma2(w0[4 * i + 3], h2.y, a1);
            d1 = fma2(w1[4 * i + 3], h2.y, d1);
        }
        float pre0 = fmaf(v[0], wx0, bias0) + hsum2(add2(a0, a1));
        float pre1 = fmaf(v[0], wx1, bias1) + hsum2(add2(d0, d1));

        float act0 = sig_ap(pre0);                              // i or f
        float act1 = low ? tanh_ap(pre1) : sig_ap(pre1);        // g or o
        if (!low) act_sh[unit] = make_float2(act0, act1);       // (f,o)

        v[0] = v[1]; v[1] = v[2]; v[2] = v[3];
        {
            int tn = (t + 4 < TT) ? (t + 4) : (TT - 1);
            v[3] = __ldg(x + xb + tn);
        }
        __syncthreads();   // gates staged; h reads done

        if (low) {
            float2 fo = act_sh[unit];
            c = fmaf(fo.x, c, act0 * act1);
            float hv = fo.y * tanh_ap(c);
            h_sh[unit] = hv;
            g_y0h[yb + (size_t)t * HH + unit] = __float2half_rn(hv);
        }
        __syncthreads();   // h ready
    }
}

// ---------------- K2: xp = y0 @ Wih1^T, coalesced fp16 output --------------
#define K2_ROWS 64
__global__ __launch_bounds__(256, 2) void xp_gemm_kernel(const float* __restrict__ Wih1)
{
    __shared__ __align__(16) float ys[K2_ROWS * HH];
    const int g = threadIdx.x;

    u64 w[32];
    {
        const ulonglong2* wr = (const ulonglong2*)(Wih1 + (size_t)g * HH);
#pragma unroll
        for (int i = 0; i < 16; i++) {
            ulonglong2 v = wr[i];
            w[2 * i]     = v.x;
            w[2 * i + 1] = v.y;
        }
    }

    const size_t r0 = (size_t)blockIdx.x * K2_ROWS;
    {
        const __half2* src = (const __half2*)(g_y0h + r0 * HH);
        float2* dst = (float2*)ys;
#pragma unroll
        for (int i = 0; i < 8; i++) {
            __half2 v = src[g + i * 256];
            dst[g + i * 256] = __half22float2(v);
        }
    }
    __syncthreads();

#pragma unroll 1
    for (int r = 0; r < K2_ROWS; r++) {
        const ulonglong2* hs = (const ulonglong2*)(ys + r * HH);
        u64 a0 = 0ull, a1 = 0ull, a2 = 0ull, a3 = 0ull;
#pragma unroll
        for (int i = 0; i < 8; i++) {
            ulonglong2 h1 = hs[2 * i];
            ulonglong2 h2 = hs[2 * i + 1];
            a0 = fma2(w[4 * i + 0], h1.x, a0);
            a1 = fma2(w[4 * i + 1], h1.y, a1);
            a2 = fma2(w[4 * i + 2], h2.x, a2);
            a3 = fma2(w[4 * i + 3], h2.y, a3);
        }
        a0 = add2(a0, a1);
        a2 = add2(a2, a3);
        a0 = add2(a0, a2);
        g_xp1[(r0 + r) * GG + g] = __float2half_rn(hsum2(a0));   // coalesced
    }
}

// ---------------- Layer 1: xp via 8-step-block cp.async ring ----------------
// The per-SM L1tex queue is shared by LDS and global wavefronts; injecting
// DRAM traffic every step makes the critical-path LDS queue behind it. Fix:
// fetch xp in 4KB blocks (8 steps x 512B) once every 8 steps -> 7 of 8 steps
// have an L0-clean LSU pipe. Ring of 4 blocks (16KB smem), issued 3 blocks
// ahead; cp.async is NOT drained by bar.sync (PTX), waits via wait_group 3.
#define BLK 8
#define NBLK (TT / BLK)   // 256
__global__ __launch_bounds__(128, 2) void lstm_l1_kernel(
    const float* __restrict__ Whh,   // Whh1 [256,64]
    const float* __restrict__ bih,
    const float* __restrict__ bhh,
    const float* __restrict__ h0,    // [B,64] layer1 slice
    const float* __restrict__ c0)    // [B,64]
{
    __shared__ __align__(16) float  h_sh[HH];
    __shared__ __align__(8)  float2 act_sh[HH];        // (f,o) per unit
    __shared__ __align__(16) __half xbuf[4][BLK][GG];  // 16KB xp ring

    const int tid  = threadIdx.x;
    const int b    = blockIdx.x;
    const int g0   = tid;
    const int g1   = tid + 128;
    const int unit = tid & 63;
    const bool low = (tid < 64);

    u64 w0[32], w1[32];
    {
        const ulonglong2* r0 = (const ulonglong2*)(Whh + (size_t)g0 * HH);
        const ulonglong2* r1 = (const ulonglong2*)(Whh + (size_t)g1 * HH);
#pragma unroll
        for (int i = 0; i < 16; i++) {
            ulonglong2 v0 = r0[i];
            ulonglong2 v1 = r1[i];
            w0[2 * i] = v0.x; w0[2 * i + 1] = v0.y;
            w1[2 * i] = v1.x; w1[2 * i + 1] = v1.y;
        }
    }
    const float bias0 = bih[g0] + bhh[g0];
    const float bias1 = bih[g1] + bhh[g1];

    float c = 0.0f;
    if (low) {
        h_sh[unit] = h0[(size_t)b * HH + unit];
        c          = c0[(size_t)b * HH + unit];
    }

    const size_t yb = (size_t)b * TT * HH;
    const __half* xsrc = g_xp1 + (size_t)b * TT * GG;   // 256 halves per step

    // prologue: blocks 0..2 (each 4KB = 128 threads x 2 x 16B, one commit)
#pragma unroll
    for (int kb = 0; kb < 3; kb++) {
        uint32_t base = smem_u32(&xbuf[kb][0][0]);
        const __half* src = xsrc + (size_t)kb * BLK * GG;
        cp_async16(base + tid * 16,        src + tid * 8);
        cp_async16(base + 2048 + tid * 16, src + 1024 + tid * 8);
        cp_commit();
    }
    cp_wait<2>();   // block 0 resident
    __syncthreads();

#pragma unroll 8
    for (int t = 0; t < TT; t++) {
        // ---- block boundary: issue block (t/8)+3, pin block t/8 ----
        if ((t & (BLK - 1)) == 0) {
            const int nb = (t >> 3) + 3;
            if (nb < NBLK) {
                uint32_t base = smem_u32(&xbuf[nb & 3][0][0]);
                const __half* src = xsrc + (size_t)nb * BLK * GG;
                cp_async16(base + tid * 16,        src + tid * 8);
                cp_async16(base + 2048 + tid * 16, src + 1024 + tid * 8);
                cp_commit();
            }
            cp_wait<3>();   // current block (t/8) resident
            __syncthreads();
        }

        // ---- recurrent dots (critical path) ----
        u64 a0 = 0ull, a1 = 0ull, d0 = 0ull, d1 = 0ull;
        const ulonglong2* hs = (const ulonglong2*)h_sh;
#pragma unroll
        for (int i = 0; i < 8; i++) {
            ulonglong2 h1 = hs[2 * i];
            ulonglong2 h2 = hs[2 * i + 1];
            a0 = fma2(w0[4 * i + 0], h1.x, a0);
            d0 = fma2(w1[4 * i + 0], h1.x, d0);
            a1 = fma2(w0[4 * i + 1], h1.y, a1);
            d1 = fma2(w1[4 * i + 1], h1.y, d1);
            a0 = fma2(w0[4 * i + 2], h2.x, a0);
            d0 = fma2(w1[4 * i + 2], h2.x, d0);
            a1 = fma2(w0[4 * i + 3], h2.y, a1);
            d1 = fma2(w1[4 * i + 3], h2.y, d1);
        }
        const __half* xrow = &xbuf[(t >> 3) & 3][t & (BLK - 1)][0];
        float xp0 = __half2float(xrow[g0]);
        float xp1 = __half2float(xrow[g1]);
        float pre0 = (bias0 + xp0) + hsum2(add2(a0, a1));
        float pre1 = (bias1 + xp1) + hsum2(add2(d0, d1));

        float act0 = sig_ap(pre0);                              // i or f
        float act1 = low ? tanh_ap(pre1) : sig_ap(pre1);        // g or o
        if (!low) act_sh[unit] = make_float2(act0, act1);       // (f,o)

        __syncthreads();   // bar1: gates staged; h reads done

        if (low) {
            float2 fo = act_sh[unit];
            c = fmaf(fo.x, c, act0 * act1);
            float hv = fo.y * tanh_ap(c);
            h_sh[unit] = hv;
            g_y1[yb + (size_t)t * HH + unit] = hv;
        }
        __syncthreads();   // bar2: h ready
    }
}

// ---------------- out: pred = y1 @ Wlin^T + blin ----------------
__global__ __launch_bounds__(256) void out_kernel(
    const float* __restrict__ Wlin,
    const float* __restrict__ blin,
    float* __restrict__ out)
{
    __shared__ __align__(16) float wl[HH];
    const int tid = threadIdx.x;
    if (tid < HH) wl[tid] = Wlin[tid];
    __syncthreads();

    const size_t idx = (size_t)blockIdx.x * 256 + tid;
    const ulonglong2* row = (const ulonglong2*)(g_y1 + idx * HH);
    const ulonglong2* wv  = (const ulonglong2*)wl;
    u64 a0 = 0ull, a1 = 0ull, a2 = 0ull, a3 = 0ull;
#pragma unroll
    for (int i = 0; i < 8; i++) {
        ulonglong2 h1 = row[2 * i];
        ulonglong2 w1 = wv[2 * i];
        ulonglong2 h2 = row[2 * i + 1];
        ulonglong2 w2 = wv[2 * i + 1];
        a0 = fma2(w1.x, h1.x, a0);
        a1 = fma2(w1.y, h1.y, a1);
        a2 = fma2(w2.x, h2.x, a2);
        a3 = fma2(w2.y, h2.y, a3);
    }
    a0 = add2(a0, a1);
    a2 = add2(a2, a3);
    a0 = add2(a0, a2);
    out[idx] = hsum2(a0) + __ldg(blin);
}

// ---------------- launch ----------------
extern "C" void kernel_launch(void* const* d_in, const int* in_sizes, int n_in,
                              void* d_out, int out_size)
{
    const float* input = (const float*)d_in[0];   // [B,T]
    const float* h0    = (const float*)d_in[1];   // [2,B,H]
    const float* c0    = (const float*)d_in[2];   // [2,B,H]
    const float* Wih0  = (const float*)d_in[3];   // [256,1]
    const float* Whh0  = (const float*)d_in[4];   // [256,64]
    const float* bih0  = (const float*)d_in[5];
    const float* bhh0  = (const float*)d_in[6];
    const float* Wih1  = (const float*)d_in[7];   // [256,64]
    const float* Whh1  = (const float*)d_in[8];   // [256,64]
    const float* bih1  = (const float*)d_in[9];
    const float* bhh1  = (const float*)d_in[10];
    const float* Wlin  = (const float*)d_in[11];  // [1,64]
    const float* blin  = (const float*)d_in[12];  // [1]
    float* out = (float*)d_out;                   // [B,T]

    (void)in_sizes; (void)n_in; (void)out_size;

    // Layer 0 -> g_y0h (fp16)
    lstm_l0_kernel<<<BB, 128>>>(input, Wih0, Whh0, bih0, bhh0, h0, c0);
    // xp = y0 @ Wih1^T -> g_xp1 (fp16, coalesced)
    xp_gemm_kernel<<<(BB * TT) / K2_ROWS, 256>>>(Wih1);
    // Layer 1 (8-step-block cp.async xp ring) -> g_y1
    lstm_l1_kernel<<<BB, 128>>>(Whh1, bih1, bhh1,
                                h0 + (size_t)BB * HH, c0 + (size_t)BB * HH);
    // pred = y1 @ Wlin^T + blin
    out_kernel<<<(BB * TT) / 256, 256>>>(Wlin, blin, out);
}